// round 14
// baseline (speedup 1.0000x reference)
#include <cuda_runtime.h>
#include <cuda_fp16.h>
#include <cstdint>

#define N_ROWS 16384
#define DIMS   128          // bytes per row in fp8
#define SEGS   16           // column segments; each warp owns band x segment
#define TPW    16           // tiles (64-col) per warp
#define WSM    16384        // smem bytes per warp (2 x 8KB buffers)

// exp(-sim/0.5) = 2^(sim * -2*log2(e)); fold scale into B at quantize time.
#define BSCALE (-2.8853900817779268f)

#define CPA16(dst_u32, src_ptr) \
    asm volatile("cp.async.cg.shared.global [%0], [%1], 16;" :: "r"(dst_u32), "l"(src_ptr))

// Scratch (allocation-free rule: device globals). Rows are chunk-permuted fp8.
__device__ unsigned char g_A[N_ROWS * DIMS];
__device__ unsigned char g_B[N_ROWS * DIMS];
__device__ __half g_labh[N_ROWS];
__device__ int    g_lab64_flag;
__device__ double g_acc;

// ---------------------------------------------------------------------------
// Kernel 1: L2-normalize rows, convert to e4m3, store chunk-permuted.
// ---------------------------------------------------------------------------
__global__ void normalize_kernel(const float* __restrict__ a,
                                 const float* __restrict__ b) {
    int w    = (blockIdx.x * blockDim.x + threadIdx.x) >> 5;
    int lane = threadIdx.x & 31;
    if (w >= 2 * N_ROWS) return;
    const float* src;
    unsigned char* dst;
    float extra;
    if (w < N_ROWS) { src = a + (size_t)w * 128; dst = g_A + (size_t)w * DIMS; extra = 1.f; }
    else { src = b + (size_t)(w - N_ROWS) * 128; dst = g_B + (size_t)(w - N_ROWS) * DIMS; extra = BSCALE; }

    float4 v = ((const float4*)src)[lane];
    float ss = v.x * v.x + v.y * v.y + v.z * v.z + v.w * v.w;
#pragma unroll
    for (int o = 16; o; o >>= 1) ss += __shfl_xor_sync(0xffffffffu, ss, o);
    float inv = rsqrtf(fmaxf(ss, 1e-24f)) * extra;
    float x0 = v.x * inv, x1 = v.y * inv, x2 = v.z * inv, x3 = v.w * inv;

    unsigned short p01, p23;  // cvt packs: low byte <- second operand
    asm("cvt.rn.satfinite.e4m3x2.f32 %0, %1, %2;" : "=h"(p01) : "f"(x1), "f"(x0));
    asm("cvt.rn.satfinite.e4m3x2.f32 %0, %1, %2;" : "=h"(p23) : "f"(x3), "f"(x2));
    uint32_t word = (uint32_t)p01 | ((uint32_t)p23 << 16);

    int wpos = (4 * (lane >> 4) + (lane & 3)) * 4 + ((lane >> 2) & 3);
    ((uint32_t*)dst)[wpos] = word;
}

// ---------------------------------------------------------------------------
// Kernel 2a/2b: label dtype detection (int64 vs int32) + conversion to half
// ---------------------------------------------------------------------------
__global__ void label_detect_kernel(const long long* __restrict__ lab) {
    int i = blockIdx.x * blockDim.x + threadIdx.x;
    if (i == 0) { g_lab64_flag = 1; g_acc = 0.0; }
    __threadfence();
    if (i < 8192) {
        long long v = lab[i];
        if (v < 0 || v >= 1000000) atomicExch(&g_lab64_flag, 0);
    }
}
__global__ void label_convert_kernel(const void* __restrict__ lab) {
    int i = blockIdx.x * blockDim.x + threadIdx.x;
    if (i < N_ROWS) {
        int l;
        if (g_lab64_flag) l = (int)((const long long*)lab)[i];
        else              l = ((const int*)lab)[i];
        g_labh[i] = __int2half_rn(l);
    }
}

// ---------------------------------------------------------------------------
// Per-lane prefetch of one 64x128B B tile into this warp's smem buffer.
// Each lane copies EXACTLY the 16 chunks it will later read itself, so
// per-thread cp.async.wait_group fully orders producer->consumer: no barrier.
// XOR-64 swizzle on odd rows makes the later LDS.128 bank-conflict-free.
// ---------------------------------------------------------------------------
__device__ __forceinline__ void prefetch_tile(uint32_t dstbase,
                                              const unsigned char* bBase,
                                              int grp, int tig) {
#pragma unroll
    for (int ni = 0; ni < 8; ni++) {
        const int r = ni * 8 + grp;
        const int sw = (grp & 1) * 64;
#pragma unroll
        for (int t = 0; t < 2; t++) {
            uint32_t dst = dstbase + r * 128 + ((t * 64 + tig * 16) ^ sw);
            CPA16(dst, bBase + (size_t)r * 128 + t * 64 + tig * 16);
        }
    }
    asm volatile("cp.async.commit_group;" ::: "memory");
}

// ---------------------------------------------------------------------------
// Kernel 3: warp-autonomous fused fp8 GEMM (f16 acc) + exp2/mask/sum, with
// per-warp double-buffered cp.async B prefetch (no __syncthreads anywhere in
// the loop). 128 threads = 4 warps/CTA, 16KB smem/warp -> 64KB/CTA -> 3 CTAs
// per SM (12 warps) with a 170-reg budget (working set ~120: no spill).
// Each warp: 32-row A band (regs) x 16 tiles of 64 B-cols.
// ---------------------------------------------------------------------------
__global__ void __launch_bounds__(128, 3) gemm_loss_kernel() {
    extern __shared__ char sm[];
    const int tid  = threadIdx.x;
    const int wid  = tid >> 5;
    const int lane = tid & 31;
    const int grp  = lane >> 2;         // 0..7
    const int tig  = lane & 3;          // 0..3

    const uint32_t wbase =
        (uint32_t)__cvta_generic_to_shared(sm) + wid * WSM;

    const int gwarp = blockIdx.x * 4 + wid;      // 0..8191
    const int band  = gwarp >> 4;                // 0..511 : 32-row A band
    const int seg   = gwarp & (SEGS - 1);        // 0..15  : 1024-col B segment
    const int col0s = seg * 1024;

    // ---- cache A fragments: 32 rows x K=128 fp8 (32 regs) ----
    uint4 Af[2][4];
#pragma unroll
    for (int rh = 0; rh < 4; rh++)
#pragma unroll
        for (int t = 0; t < 2; t++)
            Af[t][rh] = *(const uint4*)(g_A +
                (size_t)(band * 32 + grp + 8 * rh) * DIMS + t * 64 + tig * 16);

    const int r0 = band * 32 + grp;
    __half2 la2[4];
#pragma unroll
    for (int j = 0; j < 4; j++) la2[j] = __half2half2(g_labh[r0 + 8 * j]);

    // ---- prime pipeline: tiles 0, 1 ----
    prefetch_tile(wbase,        g_B + (size_t)col0s * DIMS,          grp, tig);
    prefetch_tile(wbase + 8192, g_B + (size_t)(col0s + 64) * DIMS,   grp, tig);

    const uint32_t uz = 0u;
    float local = 0.f;
#pragma unroll 1
    for (int it = 0; it < TPW; it++) {
        const int col0 = col0s + it * 64;

        // labels (L1-resident after first wave; issued early to overlap)
        __half2 lb2[8];
#pragma unroll
        for (int ni = 0; ni < 8; ni++)
            lb2[ni] = *(const __half2*)(g_labh + col0 + ni * 8 + 2 * tig);

        if (it < TPW - 1) { asm volatile("cp.async.wait_group 1;" ::: "memory"); }
        else              { asm volatile("cp.async.wait_group 0;" ::: "memory"); }

        const uint32_t buf = wbase + (it & 1) * 8192;
        const uint32_t sw  = (grp & 1) * 64;

        uint32_t acc[2][8][2];       // written by first MMA (zero-C), no init
        uint4 Bf[8];

        // ---- t = 0: LDS fragments, then 32 MMAs (s=0 uses C={0,0}) ----
#pragma unroll
        for (int ni = 0; ni < 8; ni++) {
            uint32_t addr = buf + (ni * 8 + grp) * 128 + ((tig * 16) ^ sw);
            asm volatile("ld.shared.v4.u32 {%0,%1,%2,%3}, [%4];"
                         : "=r"(Bf[ni].x), "=r"(Bf[ni].y), "=r"(Bf[ni].z), "=r"(Bf[ni].w)
                         : "r"(addr));
        }
#pragma unroll
        for (int s = 0; s < 2; s++) {
#pragma unroll
            for (int ni = 0; ni < 8; ni++) {
                const uint32_t* B_w = (const uint32_t*)&Bf[ni];
#pragma unroll
                for (int mi = 0; mi < 2; mi++) {
                    const uint32_t* A0 = (const uint32_t*)&Af[0][2 * mi];
                    const uint32_t* A1 = (const uint32_t*)&Af[0][2 * mi + 1];
                    if (s == 0) {
                        asm volatile(
                            "mma.sync.aligned.m16n8k32.row.col.f16.e4m3.e4m3.f16 "
                            "{%0,%1}, {%2,%3,%4,%5}, {%6,%7}, {%8,%8};"
                            : "=r"(acc[mi][ni][0]), "=r"(acc[mi][ni][1])
                            : "r"(A0[0]), "r"(A1[0]), "r"(A0[1]), "r"(A1[1]),
                              "r"(B_w[0]), "r"(B_w[1]), "r"(uz));
                    } else {
                        asm volatile(
                            "mma.sync.aligned.m16n8k32.row.col.f16.e4m3.e4m3.f16 "
                            "{%0,%1}, {%2,%3,%4,%5}, {%6,%7}, {%0,%1};"
                            : "+r"(acc[mi][ni][0]), "+r"(acc[mi][ni][1])
                            : "r"(A0[2]), "r"(A1[2]), "r"(A0[3]), "r"(A1[3]),
                              "r"(B_w[2]), "r"(B_w[3]));
                    }
                }
            }
        }

        // ---- t = 1: LDS fragments, kick prefetch of tile it+2, 32 MMAs ----
#pragma unroll
        for (int ni = 0; ni < 8; ni++) {
            uint32_t addr = buf + (ni * 8 + grp) * 128 + ((64 + tig * 16) ^ sw);
            asm volatile("ld.shared.v4.u32 {%0,%1,%2,%3}, [%4];"
                         : "=r"(Bf[ni].x), "=r"(Bf[ni].y), "=r"(Bf[ni].z), "=r"(Bf[ni].w)
                         : "r"(addr));
        }
        if (it + 2 < TPW)   // buffer (it&1) fully consumed after the LDS above
            prefetch_tile(wbase + (it & 1) * 8192,
                          g_B + (size_t)(col0s + (it + 2) * 64) * DIMS, grp, tig);
#pragma unroll
        for (int s = 0; s < 2; s++) {
#pragma unroll
            for (int ni = 0; ni < 8; ni++) {
                const uint32_t* B_w = (const uint32_t*)&Bf[ni];
#pragma unroll
                for (int mi = 0; mi < 2; mi++) {
                    const uint32_t* A0 = (const uint32_t*)&Af[1][2 * mi];
                    const uint32_t* A1 = (const uint32_t*)&Af[1][2 * mi + 1];
                    asm volatile(
                        "mma.sync.aligned.m16n8k32.row.col.f16.e4m3.e4m3.f16 "
                        "{%0,%1}, {%2,%3,%4,%5}, {%6,%7}, {%0,%1};"
                        : "+r"(acc[mi][ni][0]), "+r"(acc[mi][ni][1])
                        : "r"(A0[2 * s]), "r"(A1[2 * s]),
                          "r"(A0[2 * s + 1]), "r"(A1[2 * s + 1]),
                          "r"(B_w[2 * s]), "r"(B_w[2 * s + 1]));
                }
            }
        }

        // ---- epilogue: sum 2^acc over label-differing pairs (all-f16x2) ----
        __half2 ts0 = __float2half2_rn(0.f), ts1 = ts0;
#pragma unroll
        for (int mi = 0; mi < 2; mi++) {
#pragma unroll
            for (int ni = 0; ni < 8; ni++) {
                __half2 e0 = h2exp2(*(const __half2*)&acc[mi][ni][0]);
                __half2 e1 = h2exp2(*(const __half2*)&acc[mi][ni][1]);
                __half2 m0 = __hne2(la2[2 * mi], lb2[ni]);
                __half2 m1 = __hne2(la2[2 * mi + 1], lb2[ni]);
                ts0 = __hfma2(e0, m0, ts0);
                ts1 = __hfma2(e1, m1, ts1);
            }
        }
        __half2 tsum = __hadd2(ts0, ts1);
        local += __low2float(tsum) + __high2float(tsum);
    }

    // ---- block reduction + single atomic (only CTA sync point) ----
#pragma unroll
    for (int o = 16; o; o >>= 1) local += __shfl_xor_sync(0xffffffffu, local, o);
    __shared__ float red[4];
    if (lane == 0) red[wid] = local;
    __syncthreads();
    if (tid == 0)
        atomicAdd(&g_acc, (double)(red[0] + red[1] + red[2] + red[3]));
}

// ---------------------------------------------------------------------------
// Kernel 4: finalize scalar
// ---------------------------------------------------------------------------
__global__ void finalize_kernel(float* __restrict__ out) {
    out[0] = (float)(g_acc / ((double)N_ROWS * (double)(N_ROWS - 1)));
}

extern "C" void kernel_launch(void* const* d_in, const int* in_sizes, int n_in,
                              void* d_out, int out_size) {
    const float* a   = (const float*)d_in[0];
    const float* b   = (const float*)d_in[1];
    const void*  lab = d_in[2];
    float* out = (float*)d_out;

    normalize_kernel<<<(2 * N_ROWS * 32) / 256, 256>>>(a, b);
    label_detect_kernel<<<(8192 + 255) / 256, 256>>>((const long long*)lab);
    label_convert_kernel<<<(N_ROWS + 255) / 256, 256>>>(lab);

    cudaFuncSetAttribute(gemm_loss_kernel,
                         cudaFuncAttributeMaxDynamicSharedMemorySize, 4 * WSM);
    // 8192 warps = 2048 CTAs x 4 warps; each warp: 32-row band x 16 tiles
    gemm_loss_kernel<<<2048, 128, 4 * WSM>>>();

    finalize_kernel<<<1, 1>>>(out);
}